// round 1
// baseline (speedup 1.0000x reference)
#include <cuda_runtime.h>

#define MTOT 8192
#define LW   64      // ww
#define RW   100     // WP*WP
#define CD   128
#define CF   120     // C - SLICE

typedef unsigned long long ull;

__device__ __forceinline__ ull pack2(float x, float y) {
    ull r; asm("mov.b64 %0, {%1,%2};" : "=l"(r) : "f"(x), "f"(y)); return r;
}
__device__ __forceinline__ float2 unpack2(ull p) {
    float2 f; asm("mov.b64 {%0,%1}, %2;" : "=f"(f.x), "=f"(f.y) : "l"(p)); return f;
}
__device__ __forceinline__ void ffma2(ull& d, ull a, ull b) {
    asm("fma.rn.f32x2 %0, %1, %2, %0;" : "+l"(d) : "l"(a), "l"(b));
}

// shared memory layout (in floats)
#define OFF_F0   0        // 8192   : feat0 row, raw [l][c]
#define OFF_F1   8192     // 16384  : feat1 row, transposed+swizzled [c][r^e]
#define OFF_CONF 24576    // 64*102 : conf_f [l][r], stride 102
#define CSTR     102
#define OFF_RMAX 31104    // 64
#define OFF_RINV 31168    // 64
#define OFF_CMAX 31232    // 112 (100 used)
#define OFF_CINV 31344    // 112
#define OFF_REDV 31456    // 256
#define OFF_REDI 31712    // 256 (ints)
#define SMEM_FLOATS 31968
#define SMEM_BYTES (SMEM_FLOATS * 4)

__global__ void __launch_bounds__(256, 1)
fine_matching_kernel(const float* __restrict__ feat0,
                     const float* __restrict__ feat1,
                     const float* __restrict__ mk0,
                     const float* __restrict__ mk1,
                     float* __restrict__ out)
{
    extern __shared__ float smem[];
    float* f0s  = smem + OFF_F0;
    float* f1sT = smem + OFF_F1;
    float* conf = smem + OFF_CONF;
    float* rmax = smem + OFF_RMAX;
    float* rinv = smem + OFF_RINV;
    float* cmax = smem + OFF_CMAX;
    float* cinv = smem + OFF_CINV;
    float* redv = smem + OFF_REDV;
    int*   redi = (int*)(smem + OFF_REDI);

    const int m    = blockIdx.x;
    const int tid  = threadIdx.x;
    const int warp = tid >> 5;
    const int lane = tid & 31;

    // prefetch mkpts (only thread 0 needs them)
    float mk0x = 0.f, mk0y = 0.f, mk1x = 0.f, mk1y = 0.f;
    if (tid == 0) {
        mk0x = mk0[2 * m]; mk0y = mk0[2 * m + 1];
        mk1x = mk1[2 * m]; mk1y = mk1[2 * m + 1];
    }

    // ---- stage feat0 row (raw layout, float4) ----
    const float4* g0 = (const float4*)(feat0 + (size_t)m * (LW * CD));
    #pragma unroll
    for (int i = 0; i < (LW * CD / 4) / 256; ++i)
        ((float4*)f0s)[tid + i * 256] = g0[tid + i * 256];

    // ---- zero the r>=100 pad region of f1sT (disjoint from staged cells) ----
    for (int t = tid; t < 128 * 28; t += 256) {
        int c  = t / 28;
        int rr = 100 + t % 28;
        int e  = ((c >> 2) & 31) << 1;
        f1sT[c * 128 + (rr ^ e)] = 0.f;
    }

    // ---- stage feat1 row: transpose + swizzle + fold scales ----
    // conf_f = dot(:120)/128 ; conf_ff = dot(120:)/sqrt(8); scales folded into f1
    const float4* g1 = (const float4*)(feat1 + (size_t)m * (RW * CD));
    for (int i4 = tid; i4 < (RW * CD) / 4; i4 += 256) {
        float4 v  = g1[i4];
        int  flat = i4 * 4;
        int  r    = flat >> 7;
        int  c0   = flat & 127;
        float s   = (c0 < CF) ? (1.0f / 128.0f) : 0.35355339059327373f;
        int  e    = ((c0 >> 2) & 31) << 1;   // same for c0..c0+3
        int  rs   = r ^ e;
        f1sT[(c0 + 0) * 128 + rs] = v.x * s;
        f1sT[(c0 + 1) * 128 + rs] = v.y * s;
        f1sT[(c0 + 2) * 128 + rs] = v.z * s;
        f1sT[(c0 + 3) * 128 + rs] = v.w * s;
    }
    __syncthreads();

    // ---- mainloop: conf_f[64][100], warp tile = 8 l x (64+36) r, f32x2 accum ----
    const int l0 = warp * 8;
    const int r0 = 2 * lane;
    ull acc[8][2];
    #pragma unroll
    for (int j = 0; j < 8; ++j) { acc[j][0] = 0ull; acc[j][1] = 0ull; }

    for (int c4 = 0; c4 < CF; c4 += 4) {
        float4 a4[8];
        #pragma unroll
        for (int j = 0; j < 8; ++j)
            a4[j] = *(const float4*)&f0s[(l0 + j) * 128 + c4];
        const int e  = ((c4 >> 2) & 31) << 1;
        const int rs = r0 ^ e;
        #pragma unroll
        for (int i = 0; i < 4; ++i) {
            const float* f1c = &f1sT[(c4 + i) * 128];
            ull b0 = *(const ull*)(f1c + rs);
            ull b1 = *(const ull*)(f1c + 64 + rs);
            #pragma unroll
            for (int j = 0; j < 8; ++j) {
                float a = (i == 0) ? a4[j].x : (i == 1) ? a4[j].y
                         : (i == 2) ? a4[j].z : a4[j].w;
                ull aa = pack2(a, a);
                ffma2(acc[j][0], aa, b0);
                ffma2(acc[j][1], aa, b1);
            }
        }
    }

    // store conf (pairs r0,r0+1 and 64+r0,65+r0)
    #pragma unroll
    for (int j = 0; j < 8; ++j) {
        float2 p0 = unpack2(acc[j][0]);
        *(float2*)&conf[(l0 + j) * CSTR + r0] = p0;
        if (lane < 18) {
            float2 p1 = unpack2(acc[j][1]);
            *(float2*)&conf[(l0 + j) * CSTR + 64 + r0] = p1;
        }
    }
    __syncthreads();

    // ---- row softmax stats (axis=2, over 100 r), 8 warps x 8 rows ----
    for (int q = 0; q < 8; ++q) {
        int l = warp * 8 + q;
        const float* row = &conf[l * CSTR];
        float v0 = row[lane], v1 = row[lane + 32], v2 = row[lane + 64];
        float v3 = (lane < 4) ? row[lane + 96] : -1e30f;
        float mx = fmaxf(fmaxf(v0, v1), fmaxf(v2, v3));
        #pragma unroll
        for (int o = 16; o; o >>= 1) mx = fmaxf(mx, __shfl_xor_sync(~0u, mx, o));
        float s = __expf(v0 - mx) + __expf(v1 - mx) + __expf(v2 - mx);
        if (lane < 4) s += __expf(v3 - mx);
        #pragma unroll
        for (int o = 16; o; o >>= 1) s += __shfl_xor_sync(~0u, s, o);
        if (lane == 0) { rmax[l] = mx; rinv[l] = 1.f / s; }
    }

    // ---- col softmax stats (axis=1, over 64 l), one thread per r ----
    if (tid < RW) {
        float mx = -1e30f;
        for (int l = 0; l < LW; ++l) mx = fmaxf(mx, conf[l * CSTR + tid]);
        float s = 0.f;
        for (int l = 0; l < LW; ++l) s += __expf(conf[l * CSTR + tid] - mx);
        cmax[tid] = mx; cinv[tid] = 1.f / s;
    }
    __syncthreads();

    // ---- cropped sm write + argmax (first-occurrence tie-break) ----
    float bv = -1e30f; int bi = 0;
    float* outm = out + (size_t)m * 4096;
    #pragma unroll
    for (int e8 = 0; e8 < 16; ++e8) {
        int flat = e8 * 256 + tid;
        int l  = flat >> 6;
        int rc = flat & 63;
        int r  = (rc >> 3) * 10 + (rc & 7) + 11;   // uncropped r index
        float v = conf[l * CSTR + r];
        float s = __expf((v - rmax[l]) + (v - cmax[r])) * rinv[l] * cinv[r];
        outm[flat] = s;
        if (s > bv) { bv = s; bi = flat; }         // ascending flat per thread
    }
    redv[tid] = bv; redi[tid] = bi;
    __syncthreads();
    for (int st = 128; st > 0; st >>= 1) {
        if (tid < st) {
            float v2 = redv[tid + st]; int i2 = redi[tid + st];
            if (v2 > redv[tid] || (v2 == redv[tid] && i2 < redi[tid])) {
                redv[tid] = v2; redi[tid] = i2;
            }
        }
        __syncthreads();
    }

    // ---- epilogue: deltas + 3x3 conf_ff patch softmax (recomputed) ----
    if (tid == 0) {
        int idx = redi[0];
        int il = idx >> 6, ir = idx & 63;
        float dlx = (float)(il & 7) - 3.5f, dly = (float)(il >> 3) - 3.5f;
        float drx = (float)(ir & 7) - 3.5f, dry = (float)(ir >> 3) - 3.5f;

        float av[8];
        #pragma unroll
        for (int t = 0; t < 8; ++t) av[t] = f0s[il * 128 + CF + t];

        float p[9];
        int ib = ir >> 3, jb = ir & 7;
        #pragma unroll
        for (int di = 0; di < 3; ++di) {
            int ii = (ib + di + 9) % 10;
            #pragma unroll
            for (int dj = 0; dj < 3; ++dj) {
                int jj = (jb + dj + 9) % 10;
                int rr = ii * 10 + jj;
                float s = 0.f;
                #pragma unroll
                for (int t = 0; t < 8; ++t) {
                    int c = CF + t;
                    int e = ((c >> 2) & 31) << 1;
                    s += av[t] * f1sT[c * 128 + (rr ^ e)];
                }
                p[di * 3 + dj] = s;
            }
        }
        float mx = p[0];
        #pragma unroll
        for (int t = 1; t < 9; ++t) mx = fmaxf(mx, p[t]);
        float h[9], se = 0.f;
        #pragma unroll
        for (int t = 0; t < 9; ++t) { h[t] = __expf((p[t] - mx) * 0.1f); se += h[t]; }
        float inv = 1.f / se;
        float ex = 0.f, ey = 0.f;
        #pragma unroll
        for (int di = 0; di < 3; ++di)
            #pragma unroll
            for (int dj = 0; dj < 3; ++dj) {
                ex += h[di * 3 + dj] * (float)(dj - 1);
                ey += h[di * 3 + dj] * (float)(di - 1);
            }
        ex *= inv; ey *= inv;

        size_t base = (size_t)MTOT * 4096;
        out[base + 2 * m]     = mk0x + dlx * 2.f;
        out[base + 2 * m + 1] = mk0y + dly * 2.f;
        out[base + 2 * MTOT + 2 * m]     = mk1x + drx * 2.f + ex * 2.f;
        out[base + 2 * MTOT + 2 * m + 1] = mk1y + dry * 2.f + ey * 2.f;
    }
}

extern "C" void kernel_launch(void* const* d_in, const int* in_sizes, int n_in,
                              void* d_out, int out_size)
{
    const float* feat0 = (const float*)d_in[0];
    const float* feat1 = (const float*)d_in[1];
    const float* mk0   = (const float*)d_in[2];
    const float* mk1   = (const float*)d_in[3];
    float* out = (float*)d_out;

    cudaFuncSetAttribute(fine_matching_kernel,
                         cudaFuncAttributeMaxDynamicSharedMemorySize, SMEM_BYTES);
    fine_matching_kernel<<<MTOT, 256, SMEM_BYTES>>>(feat0, feat1, mk0, mk1, out);
}

// round 2
// speedup vs baseline: 1.5328x; 1.5328x over previous
#include <cuda_runtime.h>

#define MTOT 8192
#define LW   64      // ww
#define RW   100     // WP*WP
#define CD   128
#define CF   120     // C - SLICE

typedef unsigned long long ull;

__device__ __forceinline__ ull pack2(float x, float y) {
    ull r; asm("mov.b64 %0, {%1,%2};" : "=l"(r) : "f"(x), "f"(y)); return r;
}
__device__ __forceinline__ float2 unpack2(ull p) {
    float2 f; asm("mov.b64 {%0,%1}, %2;" : "=f"(f.x), "=f"(f.y) : "l"(p)); return f;
}
__device__ __forceinline__ void ffma2(ull& d, ull a, ull b) {
    asm("fma.rn.f32x2 %0, %1, %2, %0;" : "+l"(d) : "l"(a), "l"(b));
}

// ---- shared memory layout (floats) ----
// f1sT : 128c x 128r swizzled             [0      , 16384)
// f0s  : 64l x 128c raw; conf aliases it  [16384  , 24576)   conf: 64 x 102
// ff0  : 64l x 8 (last channels of f0)    [24576  , 25088)
// rmax/rinv: 64+64 ; cmax/cinv: 112+112 ; red: 16+16
#define OFF_F1   0
#define OFF_F0   16384
#define OFF_CONF 16384            // aliases f0s (dead after mainloop)
#define CSTR     102
#define OFF_FF0  24576
#define OFF_RMAX 25088
#define OFF_RINV 25152
#define OFF_CMAX 25216
#define OFF_CINV 25328
#define OFF_REDV 25440
#define OFF_REDI 25456
#define SMEM_FLOATS 25472
#define SMEM_BYTES (SMEM_FLOATS * 4)

__global__ void __launch_bounds__(256, 2)
fine_matching_kernel(const float* __restrict__ feat0,
                     const float* __restrict__ feat1,
                     const float* __restrict__ mk0,
                     const float* __restrict__ mk1,
                     float* __restrict__ out)
{
    extern __shared__ float smem[];
    float* f1sT = smem + OFF_F1;
    float* f0s  = smem + OFF_F0;
    float* conf = smem + OFF_CONF;   // aliases f0s
    float* ff0  = smem + OFF_FF0;
    float* rmax = smem + OFF_RMAX;
    float* rinv = smem + OFF_RINV;
    float* cmax = smem + OFF_CMAX;
    float* cinv = smem + OFF_CINV;
    float* redv = smem + OFF_REDV;
    int*   redi = (int*)(smem + OFF_REDI);

    const int m    = blockIdx.x;
    const int tid  = threadIdx.x;
    const int warp = tid >> 5;
    const int lane = tid & 31;

    // mkpts prefetch (epilogue thread only)
    float mk0x = 0.f, mk0y = 0.f, mk1x = 0.f, mk1y = 0.f;
    if (tid == 0) {
        mk0x = mk0[2 * m]; mk0y = mk0[2 * m + 1];
        mk1x = mk1[2 * m]; mk1y = mk1[2 * m + 1];
    }

    // ---- stage feat0 row (raw [l][c], float4) ----
    const float4* g0 = (const float4*)(feat0 + (size_t)m * (LW * CD));
    #pragma unroll
    for (int i = 0; i < (LW * CD / 4) / 256; ++i)
        ((float4*)f0s)[tid + i * 256] = g0[tid + i * 256];

    // ff0 copy (last 8 channels of each l row) — L1 hits
    if (tid < 128)
        ((float4*)ff0)[tid] = g0[(tid >> 1) * 32 + 30 + (tid & 1)];

    // ---- stage feat1 row: transpose + swizzle + fold scales ----
    const float4* g1 = (const float4*)(feat1 + (size_t)m * (RW * CD));
    for (int i4 = tid; i4 < (RW * CD) / 4; i4 += 256) {
        float4 v  = g1[i4];
        int  flat = i4 * 4;
        int  r    = flat >> 7;
        int  c0   = flat & 127;
        float s   = (c0 < CF) ? (1.0f / 128.0f) : 0.35355339059327373f;
        int  e    = ((c0 >> 2) & 31) << 1;
        int  rs   = r ^ e;
        f1sT[(c0 + 0) * 128 + rs] = v.x * s;
        f1sT[(c0 + 1) * 128 + rs] = v.y * s;
        f1sT[(c0 + 2) * 128 + rs] = v.z * s;
        f1sT[(c0 + 3) * 128 + rs] = v.w * s;
    }
    __syncthreads();

    // ---- mainloop: warp tile = 8 l x (64+36) r, f32x2 accumulators ----
    const int l0 = warp * 8;
    const int r0 = 2 * lane;
    ull acc[8][2];
    #pragma unroll
    for (int j = 0; j < 8; ++j) { acc[j][0] = 0ull; acc[j][1] = 0ull; }

    for (int c4 = 0; c4 < CF; c4 += 4) {
        float4 a4[8];
        #pragma unroll
        for (int j = 0; j < 8; ++j)
            a4[j] = *(const float4*)&f0s[(l0 + j) * 128 + c4];
        const int e  = ((c4 >> 2) & 31) << 1;
        const int rs = r0 ^ e;
        #pragma unroll
        for (int i = 0; i < 4; ++i) {
            const float* f1c = &f1sT[(c4 + i) * 128];
            ull b0 = *(const ull*)(f1c + rs);
            ull b1 = *(const ull*)(f1c + 64 + rs);
            #pragma unroll
            for (int j = 0; j < 8; ++j) {
                float a = (i == 0) ? a4[j].x : (i == 1) ? a4[j].y
                         : (i == 2) ? a4[j].z : a4[j].w;
                ull aa = pack2(a, a);
                ffma2(acc[j][0], aa, b0);
                ffma2(acc[j][1], aa, b1);
            }
        }
    }
    __syncthreads();   // all f0s reads done; conf may now alias it

    // store conf from registers (r >= 100 lanes hold garbage; never stored)
    #pragma unroll
    for (int j = 0; j < 8; ++j) {
        float2 p0 = unpack2(acc[j][0]);
        *(float2*)&conf[(l0 + j) * CSTR + r0] = p0;
        if (lane < 18) {
            float2 p1 = unpack2(acc[j][1]);
            *(float2*)&conf[(l0 + j) * CSTR + 64 + r0] = p1;
        }
    }
    __syncthreads();

    // ---- softmax stats, split across warps ----
    if (warp < 4) {
        // row stats (axis=2 over 100 r): warps 0-3, 16 rows each
        #pragma unroll 4
        for (int q = 0; q < 16; ++q) {
            int l = warp * 16 + q;
            const float* row = &conf[l * CSTR];
            float v0 = row[lane], v1 = row[lane + 32], v2 = row[lane + 64];
            float v3 = (lane < 4) ? row[lane + 96] : -1e30f;
            float mx = fmaxf(fmaxf(v0, v1), fmaxf(v2, v3));
            #pragma unroll
            for (int o = 16; o; o >>= 1) mx = fmaxf(mx, __shfl_xor_sync(~0u, mx, o));
            float s = __expf(v0 - mx) + __expf(v1 - mx) + __expf(v2 - mx)
                    + __expf(v3 - mx);   // exp(-huge)=0 for lane>=4
            #pragma unroll
            for (int o = 16; o; o >>= 1) s += __shfl_xor_sync(~0u, s, o);
            if (lane == 0) { rmax[l] = mx; rinv[l] = 1.f / s; }
        }
    } else {
        // col stats (axis=1 over 64 l): warps 4-7, one column per thread,
        // 4 independent chains to hide LDS latency
        int r = (warp - 4) * 32 + lane;
        if (r < RW) {
            float m0 = -1e30f, m1 = -1e30f, m2 = -1e30f, m3 = -1e30f;
            #pragma unroll
            for (int l = 0; l < LW; l += 4) {
                m0 = fmaxf(m0, conf[(l + 0) * CSTR + r]);
                m1 = fmaxf(m1, conf[(l + 1) * CSTR + r]);
                m2 = fmaxf(m2, conf[(l + 2) * CSTR + r]);
                m3 = fmaxf(m3, conf[(l + 3) * CSTR + r]);
            }
            float mx = fmaxf(fmaxf(m0, m1), fmaxf(m2, m3));
            float s0 = 0.f, s1 = 0.f, s2 = 0.f, s3 = 0.f;
            #pragma unroll
            for (int l = 0; l < LW; l += 4) {
                s0 += __expf(conf[(l + 0) * CSTR + r] - mx);
                s1 += __expf(conf[(l + 1) * CSTR + r] - mx);
                s2 += __expf(conf[(l + 2) * CSTR + r] - mx);
                s3 += __expf(conf[(l + 3) * CSTR + r] - mx);
            }
            cmax[r] = mx; cinv[r] = 1.f / ((s0 + s1) + (s2 + s3));
        }
    }
    __syncthreads();

    // ---- cropped sm write + argmax (first-occurrence tie-break) ----
    const int rc = tid & 63;
    const int r  = (rc >> 3) * 10 + (rc & 7) + 11;
    const float cm = cmax[r], ci = cinv[r];
    const int lb = tid >> 6;
    float bv = -1e30f; int bi = 0;
    float* outm = out + (size_t)m * 4096;
    #pragma unroll
    for (int e8 = 0; e8 < 16; ++e8) {
        int l = e8 * 4 + lb;
        float v = conf[l * CSTR + r];
        float s = __expf(2.f * v - rmax[l] - cm) * rinv[l] * ci;
        int flat = l * 64 + rc;
        outm[flat] = s;
        if (s > bv) { bv = s; bi = flat; }   // ascending flat per thread
    }
    // warp-level (v,i) reduce, min index on ties
    #pragma unroll
    for (int o = 16; o; o >>= 1) {
        float v2 = __shfl_xor_sync(~0u, bv, o);
        int   i2 = __shfl_xor_sync(~0u, bi, o);
        if (v2 > bv || (v2 == bv && i2 < bi)) { bv = v2; bi = i2; }
    }
    if (lane == 0) { redv[warp] = bv; redi[warp] = bi; }
    __syncthreads();

    // ---- warp 0: final reduce + epilogue ----
    if (warp == 0) {
        float v = (lane < 8) ? redv[lane] : -1e30f;
        int   i = (lane < 8) ? redi[lane] : 0x7fffffff;
        #pragma unroll
        for (int o = 4; o; o >>= 1) {
            float v2 = __shfl_xor_sync(~0u, v, o);
            int   i2 = __shfl_xor_sync(~0u, i, o);
            if (v2 > v || (v2 == v && i2 < i)) { v = v2; i = i2; }
        }
        if (lane == 0) {
            int idx = i;
            int il = idx >> 6, ir = idx & 63;
            float dlx = (float)(il & 7) - 3.5f, dly = (float)(il >> 3) - 3.5f;
            float drx = (float)(ir & 7) - 3.5f, dry = (float)(ir >> 3) - 3.5f;

            float av[8];
            #pragma unroll
            for (int t = 0; t < 8; ++t) av[t] = ff0[il * 8 + t];

            float p[9];
            int ib = ir >> 3, jb = ir & 7;
            #pragma unroll
            for (int di = 0; di < 3; ++di) {
                int ii = ib + di - 1; ii = (ii < 0) ? ii + 10 : ((ii > 9) ? ii - 10 : ii);
                #pragma unroll
                for (int dj = 0; dj < 3; ++dj) {
                    int jj = jb + dj - 1; jj = (jj < 0) ? jj + 10 : ((jj > 9) ? jj - 10 : jj);
                    int rr = ii * 10 + jj;
                    float s = 0.f;
                    #pragma unroll
                    for (int t = 0; t < 8; ++t) {
                        int c = CF + t;
                        int e = ((c >> 2) & 31) << 1;
                        s += av[t] * f1sT[c * 128 + (rr ^ e)];
                    }
                    p[di * 3 + dj] = s;
                }
            }
            float mx = p[0];
            #pragma unroll
            for (int t = 1; t < 9; ++t) mx = fmaxf(mx, p[t]);
            float h[9], se = 0.f;
            #pragma unroll
            for (int t = 0; t < 9; ++t) { h[t] = __expf((p[t] - mx) * 0.1f); se += h[t]; }
            float inv = 1.f / se;
            float ex = 0.f, ey = 0.f;
            #pragma unroll
            for (int di = 0; di < 3; ++di)
                #pragma unroll
                for (int dj = 0; dj < 3; ++dj) {
                    ex += h[di * 3 + dj] * (float)(dj - 1);
                    ey += h[di * 3 + dj] * (float)(di - 1);
                }
            ex *= inv; ey *= inv;

            size_t base = (size_t)MTOT * 4096;
            out[base + 2 * m]     = mk0x + dlx * 2.f;
            out[base + 2 * m + 1] = mk0y + dly * 2.f;
            out[base + 2 * MTOT + 2 * m]     = mk1x + drx * 2.f + ex * 2.f;
            out[base + 2 * MTOT + 2 * m + 1] = mk1y + dry * 2.f + ey * 2.f;
        }
    }
}

extern "C" void kernel_launch(void* const* d_in, const int* in_sizes, int n_in,
                              void* d_out, int out_size)
{
    const float* feat0 = (const float*)d_in[0];
    const float* feat1 = (const float*)d_in[1];
    const float* mk0   = (const float*)d_in[2];
    const float* mk1   = (const float*)d_in[3];
    float* out = (float*)d_out;

    cudaFuncSetAttribute(fine_matching_kernel,
                         cudaFuncAttributeMaxDynamicSharedMemorySize, SMEM_BYTES);
    fine_matching_kernel<<<MTOT, 256, SMEM_BYTES>>>(feat0, feat1, mk0, mk1, out);
}